// round 1
// baseline (speedup 1.0000x reference)
#include <cuda_runtime.h>
#include <cuda_bf16.h>

#define RES 7
#define NROI 1024
#define NCH 256

struct Meta {
    float x1, y1, bw, bh;
    int lvl, b;
};

__device__ Meta g_meta[NROI];

__global__ void setup_kernel(const float* __restrict__ p0,
                             const float* __restrict__ p1) {
    int r = blockIdx.x * blockDim.x + threadIdx.x;
    if (r >= NROI) return;
    const float* p = (r < 512) ? (p0 + r * 4) : (p1 + (r - 512) * 4);
    float x1 = p[0], y1 = p[1], x2 = p[2], y2 = p[3];
    float area = (x2 - x1 + 1.0f) * (y2 - y1 + 1.0f);
    float sz = sqrtf(area);
    float lv = floorf(4.0f + log2f(sz / 224.0f + 1e-6f));
    lv = fminf(fmaxf(lv, 2.0f), 5.0f);
    int lvl = (int)lv - 2;
    float scale = 0.25f / (float)(1 << lvl);
    float x1s = x1 * scale, y1s = y1 * scale;
    float x2s = x2 * scale, y2s = y2 * scale;
    float rw = fmaxf(x2s - x1s, 1.0f);
    float rh = fmaxf(y2s - y1s, 1.0f);
    Meta m;
    m.x1 = x1s; m.y1 = y1s;
    m.bw = rw / 7.0f; m.bh = rh / 7.0f;
    m.lvl = lvl; m.b = (r < 512) ? 0 : 1;
    g_meta[r] = m;
}

// gridDim = (49, 1024): blockIdx.y = roi, blockIdx.x = element chunk.
// 256 threads/block, e in [0, 49*256) covers all (c, bin) pairs for this roi.
__global__ __launch_bounds__(256) void pool_kernel(
    const float* __restrict__ f0, const float* __restrict__ f1,
    const float* __restrict__ f2, const float* __restrict__ f3,
    float* __restrict__ out) {
    int roi = blockIdx.y;

    __shared__ Meta sm;
    __shared__ const float* sbase;
    __shared__ int sH, sW;
    if (threadIdx.x == 0) {
        Meta m = g_meta[roi];
        sm = m;
        const float* base;
        int H, W;
        switch (m.lvl) {
            case 0:  base = f0; H = 200; W = 200; break;
            case 1:  base = f1; H = 100; W = 100; break;
            case 2:  base = f2; H = 50;  W = 50;  break;
            default: base = f3; H = 25;  W = 25;  break;
        }
        sbase = base + (size_t)m.b * NCH * H * W;
        sH = H; sW = W;
    }
    __syncthreads();

    const Meta m = sm;
    const float* base = sbase;
    const int H = sH, W = sW;

    int e = blockIdx.x * 256 + threadIdx.x;   // [0, 12544)
    int c = e / 49;
    int bin = e - c * 49;
    int py = bin / 7;
    int px = bin - py * 7;

    const float* cbase = base + (size_t)c * H * W;

    float acc = 0.0f;
#pragma unroll
    for (int iy = 0; iy < 2; iy++) {
        float yy = m.y1 + ((float)(py * 2 + iy) + 0.5f) * 0.5f * m.bh;
        bool vy = (yy >= -1.0f) && (yy <= (float)H);
        float y0 = fmaxf(yy, 0.0f);
        int yl = (int)floorf(y0);
        int yh; float fy;
        if (yl >= H - 1) { yl = H - 1; yh = H - 1; fy = 0.0f; }
        else             { yh = yl + 1; fy = y0 - (float)yl; }
        float hy = 1.0f - fy;
        const float* rl = cbase + (size_t)yl * W;
        const float* rh = cbase + (size_t)yh * W;
#pragma unroll
        for (int ix = 0; ix < 2; ix++) {
            float xx = m.x1 + ((float)(px * 2 + ix) + 0.5f) * 0.5f * m.bw;
            bool vx = (xx >= -1.0f) && (xx <= (float)W);
            float x0 = fmaxf(xx, 0.0f);
            int xl = (int)floorf(x0);
            int xh; float fx;
            if (xl >= W - 1) { xl = W - 1; xh = W - 1; fx = 0.0f; }
            else             { xh = xl + 1; fx = x0 - (float)xl; }
            float hx = 1.0f - fx;
            if (vy && vx) {
                float v = (__ldg(rl + xl) * hx + __ldg(rl + xh) * fx) * hy
                        + (__ldg(rh + xl) * hx + __ldg(rh + xh) * fx) * fy;
                acc += v;
            }
        }
    }

    out[((size_t)roi * NCH + c) * 49 + bin] = acc * 0.25f;
}

extern "C" void kernel_launch(void* const* d_in, const int* in_sizes, int n_in,
                              void* d_out, int out_size) {
    const float* f0 = (const float*)d_in[0];
    const float* f1 = (const float*)d_in[1];
    const float* f2 = (const float*)d_in[2];
    const float* f3 = (const float*)d_in[3];
    // d_in[4] = feat4 (13x13) — never selected by the 4 RATIOS; unused.
    const float* p0 = (const float*)d_in[5];
    const float* p1 = (const float*)d_in[6];
    float* out = (float*)d_out;

    setup_kernel<<<4, 256>>>(p0, p1);
    dim3 grid(49, NROI);
    pool_kernel<<<grid, 256>>>(f0, f1, f2, f3, out);
}